// round 1
// baseline (speedup 1.0000x reference)
#include <cuda_runtime.h>
#include <cuda_bf16.h>
#include <cstdint>

// Problem constants (fixed by the reference setup)
#define BSZ   4
#define LSEQ  2048
#define DM    2048
#define NS    16
#define ETOT  (DM + 2 * NS)     // 2080
#define MTOT  (BSZ * LSEQ)      // 8192
#define KTOT  DM                // 2048

// ---------------- scratch (no cudaMalloc allowed) ----------------
__device__ float g_dt[(size_t)MTOT * DM];   // softplus(x_proj[:, :DM])  64MB
__device__ float g_bc[(size_t)MTOT * 32];   // interleaved (B_n, C_n) per row, 1MB

// ---------------- GEMM: x_proj = x @ W^T, fused softplus/split -----------
// A = x  [MTOT, KTOT] row-major
// W      [ETOT, KTOT] row-major
// out column e<DM -> g_dt (softplus), e in [DM, DM+32) -> g_bc interleaved
#define BM 128
#define BN 128
#define BKK 8
#define LDS_PAD 132

__device__ __forceinline__ float softplusf(float v) {
    return fmaxf(v, 0.0f) + log1pf(__expf(-fabsf(v)));
}

__global__ void __launch_bounds__(256)
gemm_xproj_kernel(const float* __restrict__ A, const float* __restrict__ W) {
    __shared__ float As[2][BKK][LDS_PAD];
    __shared__ float Bs[2][BKK][LDS_PAD];

    const int tid = threadIdx.x;
    const int m0 = blockIdx.y * BM;
    const int n0 = blockIdx.x * BN;

    const int loadRow = tid >> 1;        // 0..127
    const int loadK   = (tid & 1) * 4;   // 0 or 4

    const float* Aptr = A + (size_t)(m0 + loadRow) * KTOT + loadK;
    const bool wvalid = (n0 + loadRow) < ETOT;
    const float* Wptr = W + (size_t)(n0 + loadRow) * KTOT + loadK;

    const int tx = tid & 15;   // col group
    const int ty = tid >> 4;   // row group

    float c[8][8];
#pragma unroll
    for (int i = 0; i < 8; i++)
#pragma unroll
        for (int j = 0; j < 8; j++) c[i][j] = 0.0f;

    // preload tile 0
    float4 aReg = *(const float4*)Aptr;
    float4 bReg = wvalid ? *(const float4*)Wptr : make_float4(0.f, 0.f, 0.f, 0.f);
    As[0][loadK + 0][loadRow] = aReg.x;
    As[0][loadK + 1][loadRow] = aReg.y;
    As[0][loadK + 2][loadRow] = aReg.z;
    As[0][loadK + 3][loadRow] = aReg.w;
    Bs[0][loadK + 0][loadRow] = bReg.x;
    Bs[0][loadK + 1][loadRow] = bReg.y;
    Bs[0][loadK + 2][loadRow] = bReg.z;
    Bs[0][loadK + 3][loadRow] = bReg.w;
    __syncthreads();

    const int NT = KTOT / BKK;   // 256
    int cur = 0;
    for (int kt = 0; kt < NT; kt++) {
        if (kt + 1 < NT) {
            aReg = *(const float4*)(Aptr + (size_t)(kt + 1) * BKK);
            bReg = wvalid ? *(const float4*)(Wptr + (size_t)(kt + 1) * BKK)
                          : make_float4(0.f, 0.f, 0.f, 0.f);
        }
        // compute on buffer `cur`
#pragma unroll
        for (int k = 0; k < BKK; k++) {
            float a[8], b[8];
#pragma unroll
            for (int i = 0; i < 8; i++) a[i] = As[cur][k][ty * 8 + i];
#pragma unroll
            for (int j = 0; j < 8; j++) b[j] = Bs[cur][k][tx * 8 + j];
#pragma unroll
            for (int i = 0; i < 8; i++)
#pragma unroll
                for (int j = 0; j < 8; j++) c[i][j] = fmaf(a[i], b[j], c[i][j]);
        }
        if (kt + 1 < NT) {
            const int nxt = cur ^ 1;
            As[nxt][loadK + 0][loadRow] = aReg.x;
            As[nxt][loadK + 1][loadRow] = aReg.y;
            As[nxt][loadK + 2][loadRow] = aReg.z;
            As[nxt][loadK + 3][loadRow] = aReg.w;
            Bs[nxt][loadK + 0][loadRow] = bReg.x;
            Bs[nxt][loadK + 1][loadRow] = bReg.y;
            Bs[nxt][loadK + 2][loadRow] = bReg.z;
            Bs[nxt][loadK + 3][loadRow] = bReg.w;
        }
        __syncthreads();
        cur ^= 1;
    }

    // epilogue: route into dt / interleaved BC
#pragma unroll
    for (int i = 0; i < 8; i++) {
        const int m = m0 + ty * 8 + i;
#pragma unroll
        for (int j = 0; j < 8; j++) {
            const int e = n0 + tx * 8 + j;
            const float v = c[i][j];
            if (e < DM) {
                g_dt[(size_t)m * DM + e] = softplusf(v);
            } else if (e < ETOT) {
                const int pos = e - DM;                 // 0..31
                const int col = (pos < NS) ? (2 * pos) : (2 * (pos - NS) + 1);
                g_bc[(size_t)m * 32 + col] = v;
            }
        }
    }
}

// ---------------- Scan: one thread per (d-pair, state n) ----------------
// block = 64 threads: 4 groups of (16 n-lanes) x (2 d each) -> 8 d per block
// grid  = BSZ * (DM / 8) = 1024 blocks
__global__ void __launch_bounds__(64)
scan_kernel(const float* __restrict__ x, const float* __restrict__ A_log,
            const float* __restrict__ Dvec, float* __restrict__ y) {
    const int tid = threadIdx.x;
    const int n   = tid & 15;
    const int grp = tid >> 4;                  // 0..3
    const int blocksPerB = DM / 8;             // 256
    const int b = blockIdx.x / blocksPerB;
    const int d = (blockIdx.x % blocksPerB) * 8 + grp * 2;

    const float A0 = -expf(A_log[d * NS + n]);
    const float A1 = -expf(A_log[(d + 1) * NS + n]);
    const float D0 = Dvec[d];
    const float D1 = Dvec[d + 1];

    const size_t rowBase = (size_t)b * LSEQ * DM + d;
    const float2* xp  = (const float2*)(x + rowBase);
    const float2* dtp = (const float2*)(g_dt + rowBase);
    const float2* bcp = (const float2*)(g_bc + (size_t)b * LSEQ * 32 + 2 * n);
    float2* yp        = (float2*)(y + rowBase);

    const int strideX  = DM / 2;   // float2 elements per l-step
    const int strideBC = 16;       // float2 elements per l-step

    float h0 = 0.0f, h1 = 0.0f;

#pragma unroll 4
    for (int l = 0; l < LSEQ; l++) {
        const float2 xv  = *xp;
        const float2 dtv = *dtp;
        const float2 bc  = *bcp;   // bc.x = B_n, bc.y = C_n
        xp += strideX; dtp += strideX; bcp += strideBC;

        const float a0 = __expf(dtv.x * A0);
        const float a1 = __expf(dtv.y * A1);
        h0 = fmaf(a0, h0, dtv.x * bc.x * xv.x);
        h1 = fmaf(a1, h1, dtv.y * bc.x * xv.y);

        float p0 = h0 * bc.y;
        float p1 = h1 * bc.y;
        // butterfly over the 16 n-lanes (masks < 16 stay in-group)
        p0 += __shfl_xor_sync(0xffffffffu, p0, 8);
        p0 += __shfl_xor_sync(0xffffffffu, p0, 4);
        p0 += __shfl_xor_sync(0xffffffffu, p0, 2);
        p0 += __shfl_xor_sync(0xffffffffu, p0, 1);
        p1 += __shfl_xor_sync(0xffffffffu, p1, 8);
        p1 += __shfl_xor_sync(0xffffffffu, p1, 4);
        p1 += __shfl_xor_sync(0xffffffffu, p1, 2);
        p1 += __shfl_xor_sync(0xffffffffu, p1, 1);

        if (n == 0) {
            float2 o;
            o.x = fmaf(D0, xv.x, p0);
            o.y = fmaf(D1, xv.y, p1);
            *yp = o;
        }
        yp += strideX;
    }
}

// ---------------- launch ----------------
extern "C" void kernel_launch(void* const* d_in, const int* in_sizes, int n_in,
                              void* d_out, int out_size) {
    const float* x      = (const float*)d_in[0];   // [4,2048,2048]
    const float* A_log  = (const float*)d_in[1];   // [2048,16]
    const float* Dvec   = (const float*)d_in[2];   // [2048]
    const float* W      = (const float*)d_in[3];   // [2080,2048]
    float* y            = (float*)d_out;           // [4,2048,2048]

    (void)in_sizes; (void)n_in; (void)out_size;

    {
        dim3 grid((ETOT + BN - 1) / BN, MTOT / BM);  // 17 x 64
        gemm_xproj_kernel<<<grid, 256>>>(x, W);
    }
    {
        dim3 grid(BSZ * (DM / 8));                   // 1024
        scan_kernel<<<grid, 64>>>(x, A_log, Dvec, y);
    }
}

// round 4
// speedup vs baseline: 1.5898x; 1.5898x over previous
#include <cuda_runtime.h>
#include <cuda_bf16.h>
#include <cstdint>

// Problem constants
#define BSZ   4
#define LSEQ  2048
#define DM    2048
#define NS    16
#define ETOT  (DM + 2 * NS)     // 2080
#define MTOT  (BSZ * LSEQ)      // 8192
#define KTOT  DM                // 2048
#define ETPAD (17 * 128)        // 2176 padded N

// ---------------- scratch (no cudaMalloc allowed) ----------------
__device__ float g_dt[(size_t)MTOT * DM];            // softplus(x_proj[:, :DM])
__device__ float g_bc[(size_t)MTOT * 32];            // interleaved (B_n, C_n) per row
__device__ __nv_bfloat16 g_xhi[(size_t)MTOT * KTOT];
__device__ __nv_bfloat16 g_xlo[(size_t)MTOT * KTOT];
__device__ __nv_bfloat16 g_whi[(size_t)ETPAD * KTOT];
__device__ __nv_bfloat16 g_wlo[(size_t)ETPAD * KTOT];

__device__ __forceinline__ float softplusf(float v) {
    return fmaxf(v, 0.0f) + log1pf(__expf(-fabsf(v)));
}

__device__ __forceinline__ uint32_t smem_u32(const void* p) {
    uint32_t a;
    asm("{ .reg .u64 t; cvta.to.shared.u64 t, %1; cvt.u32.u64 %0, t; }" : "=r"(a) : "l"(p));
    return a;
}

// SW64 swizzle for 64B rows: XOR bits [5:4] with bits [8:7]
__device__ __forceinline__ uint32_t sw64(uint32_t b) { return b ^ ((b >> 3) & 0x30); }

__device__ __forceinline__ void cp_async16(uint32_t saddr, const void* gaddr) {
    asm volatile("cp.async.cg.shared.global [%0], [%1], 16;" :: "r"(saddr), "l"(gaddr));
}
__device__ __forceinline__ void cp_commit() { asm volatile("cp.async.commit_group;"); }
template <int N>
__device__ __forceinline__ void cp_wait() { asm volatile("cp.async.wait_group %0;" :: "n"(N)); }

__device__ __forceinline__ void ldsm_x4(uint32_t* r, uint32_t addr) {
    asm volatile("ldmatrix.sync.aligned.m8n8.x4.shared.b16 {%0,%1,%2,%3}, [%4];"
                 : "=r"(r[0]), "=r"(r[1]), "=r"(r[2]), "=r"(r[3]) : "r"(addr));
}
__device__ __forceinline__ void mma16816(float* c, const uint32_t* a, const uint32_t* b) {
    asm volatile(
        "mma.sync.aligned.m16n8k16.row.col.f32.bf16.bf16.f32 "
        "{%0,%1,%2,%3}, {%4,%5,%6,%7}, {%8,%9}, {%0,%1,%2,%3};"
        : "+f"(c[0]), "+f"(c[1]), "+f"(c[2]), "+f"(c[3])
        : "r"(a[0]), "r"(a[1]), "r"(a[2]), "r"(a[3]), "r"(b[0]), "r"(b[1]));
}

// ================= split conversion kernels =================
__global__ void __launch_bounds__(256)
split_x_kernel(const float* __restrict__ x) {
    size_t i = ((size_t)blockIdx.x * blockDim.x + threadIdx.x) * 4;
    float4 v = *(const float4*)(x + i);
    __nv_bfloat16 h0 = __float2bfloat16(v.x), h1 = __float2bfloat16(v.y);
    __nv_bfloat16 h2 = __float2bfloat16(v.z), h3 = __float2bfloat16(v.w);
    __nv_bfloat16 l0 = __float2bfloat16(v.x - __bfloat162float(h0));
    __nv_bfloat16 l1 = __float2bfloat16(v.y - __bfloat162float(h1));
    __nv_bfloat16 l2 = __float2bfloat16(v.z - __bfloat162float(h2));
    __nv_bfloat16 l3 = __float2bfloat16(v.w - __bfloat162float(h3));
    __nv_bfloat162 hp0 = {h0, h1}, hp1 = {h2, h3};
    __nv_bfloat162 lp0 = {l0, l1}, lp1 = {l2, l3};
    *(uint2*)&g_xhi[i] = make_uint2(*(uint32_t*)&hp0, *(uint32_t*)&hp1);
    *(uint2*)&g_xlo[i] = make_uint2(*(uint32_t*)&lp0, *(uint32_t*)&lp1);
}

__global__ void __launch_bounds__(256)
split_w_kernel(const float* __restrict__ W) {
    size_t i = ((size_t)blockIdx.x * blockDim.x + threadIdx.x) * 4;
    size_t row = i / KTOT;
    if (row >= ETOT) {
        *(uint2*)&g_whi[i] = make_uint2(0u, 0u);
        *(uint2*)&g_wlo[i] = make_uint2(0u, 0u);
        return;
    }
    float4 v = *(const float4*)(W + i);
    __nv_bfloat16 h0 = __float2bfloat16(v.x), h1 = __float2bfloat16(v.y);
    __nv_bfloat16 h2 = __float2bfloat16(v.z), h3 = __float2bfloat16(v.w);
    __nv_bfloat16 l0 = __float2bfloat16(v.x - __bfloat162float(h0));
    __nv_bfloat16 l1 = __float2bfloat16(v.y - __bfloat162float(h1));
    __nv_bfloat16 l2 = __float2bfloat16(v.z - __bfloat162float(h2));
    __nv_bfloat16 l3 = __float2bfloat16(v.w - __bfloat162float(h3));
    __nv_bfloat162 hp0 = {h0, h1}, hp1 = {h2, h3};
    __nv_bfloat162 lp0 = {l0, l1}, lp1 = {l2, l3};
    *(uint2*)&g_whi[i] = make_uint2(*(uint32_t*)&hp0, *(uint32_t*)&hp1);
    *(uint2*)&g_wlo[i] = make_uint2(*(uint32_t*)&lp0, *(uint32_t*)&lp1);
}

// ================= HMMA GEMM =================
#define BK    32
#define NCH   (KTOT / BK)        // 64
#define TILE_B (128 * 64)        // 8KB part
#define STAGE_B (4 * TILE_B)     // 32KB
#define GEMM_SMEM (2 * STAGE_B)  // 64KB

__device__ __forceinline__ void load_part_ca(const __nv_bfloat16* __restrict__ g,
                                             int row0, int kc, uint32_t sbase, int tid) {
    const int row = tid >> 1;
    const int half = tid & 1;
    const char* src = (const char*)(g + (size_t)(row0 + row) * KTOT + kc) + half * 32;
    const uint32_t b0 = row * 64 + half * 32;
    cp_async16(sbase + sw64(b0), src);
    cp_async16(sbase + sw64(b0 + 16), src + 16);
}

__global__ void __launch_bounds__(256, 1)
gemm_hmma_kernel() {
    extern __shared__ __align__(128) char smem[];
    const uint32_t sb = smem_u32(smem);
    const int tid = threadIdx.x;
    const int wid = tid >> 5;
    const int lid = tid & 31;
    const int n0 = blockIdx.x * 128;
    const int m0 = blockIdx.y * 128;

    const int warp_m = (wid & 3) * 32;
    const int warp_n = (wid >> 2) * 64;

    float acc[2][8][4];
#pragma unroll
    for (int i = 0; i < 2; i++)
#pragma unroll
        for (int j = 0; j < 8; j++)
#pragma unroll
            for (int r = 0; r < 4; r++) acc[i][j][r] = 0.0f;

#pragma unroll
    for (int p = 0; p < 2; p++) {
        const uint32_t st = sb + p * STAGE_B;
        load_part_ca(g_xhi, m0, p * BK, st, tid);
        load_part_ca(g_xlo, m0, p * BK, st + TILE_B, tid);
        load_part_ca(g_whi, n0, p * BK, st + 2 * TILE_B, tid);
        load_part_ca(g_wlo, n0, p * BK, st + 3 * TILE_B, tid);
        cp_commit();
    }

    const uint32_t a_off = (warp_m + (lid & 15)) * 64 + (lid >> 4) * 16;
    const uint32_t b_row = (lid & 7) + ((lid >> 4) << 3);
    const uint32_t b_kh  = ((lid >> 3) & 1) * 16;

    for (int c = 0; c < NCH; c++) {
        const int s = c & 1;
        if (c == NCH - 1) cp_wait<0>(); else cp_wait<1>();
        __syncthreads();

        const uint32_t st = sb + s * STAGE_B;
#pragma unroll
        for (int ks = 0; ks < 2; ks++) {
            uint32_t a_hi[2][4], a_lo[2][4], b_hi[8][2], b_lo[8][2];
#pragma unroll
            for (int i = 0; i < 2; i++) {
                ldsm_x4(a_hi[i], st + sw64(a_off + i * 16 * 64 + ks * 32));
                ldsm_x4(a_lo[i], st + TILE_B + sw64(a_off + i * 16 * 64 + ks * 32));
            }
#pragma unroll
            for (int g = 0; g < 4; g++) {
                uint32_t r[4];
                ldsm_x4(r, st + 2 * TILE_B +
                            sw64((warp_n + g * 16 + b_row) * 64 + ks * 32 + b_kh));
                b_hi[2 * g][0] = r[0]; b_hi[2 * g][1] = r[1];
                b_hi[2 * g + 1][0] = r[2]; b_hi[2 * g + 1][1] = r[3];
                ldsm_x4(r, st + 3 * TILE_B +
                            sw64((warp_n + g * 16 + b_row) * 64 + ks * 32 + b_kh));
                b_lo[2 * g][0] = r[0]; b_lo[2 * g][1] = r[1];
                b_lo[2 * g + 1][0] = r[2]; b_lo[2 * g + 1][1] = r[3];
            }
#pragma unroll
            for (int i = 0; i < 2; i++)
#pragma unroll
                for (int j = 0; j < 8; j++) {
                    mma16816(acc[i][j], a_hi[i], b_hi[j]);
                    mma16816(acc[i][j], a_hi[i], b_lo[j]);
                    mma16816(acc[i][j], a_lo[i], b_hi[j]);
                }
        }
        __syncthreads();
        if (c + 2 < NCH) {
            const uint32_t st2 = sb + s * STAGE_B;
            load_part_ca(g_xhi, m0, (c + 2) * BK, st2, tid);
            load_part_ca(g_xlo, m0, (c + 2) * BK, st2 + TILE_B, tid);
            load_part_ca(g_whi, n0, (c + 2) * BK, st2 + 2 * TILE_B, tid);
            load_part_ca(g_wlo, n0, (c + 2) * BK, st2 + 3 * TILE_B, tid);
            cp_commit();
        }
    }

    const int row_in = lid >> 2;
    const int colp   = (lid & 3) * 2;
#pragma unroll
    for (int i = 0; i < 2; i++) {
#pragma unroll
        for (int j = 0; j < 8; j++) {
#pragma unroll
            for (int half = 0; half < 2; half++) {
                const int m = m0 + warp_m + i * 16 + row_in + half * 8;
                const int e = n0 + warp_n + j * 8 + colp;
                const float v0 = acc[i][j][half * 2];
                const float v1 = acc[i][j][half * 2 + 1];
                if (e + 1 < DM) {
                    float2 o = make_float2(softplusf(v0), softplusf(v1));
                    *(float2*)&g_dt[(size_t)m * DM + e] = o;
                } else if (e >= DM && e < ETOT) {
                    const int p0 = e - DM;
                    const int c0 = (p0 < NS) ? (2 * p0) : (2 * (p0 - NS) + 1);
                    g_bc[(size_t)m * 32 + c0] = v0;
                    if (e + 1 < ETOT) {
                        const int p1 = p0 + 1;
                        const int c1 = (p1 < NS) ? (2 * p1) : (2 * (p1 - NS) + 1);
                        g_bc[(size_t)m * 32 + c1] = v1;
                    }
                }
            }
        }
    }
}

// ================= Scan: 4 lanes per (b,d), 4 states per lane =================
__global__ void __launch_bounds__(128)
scan_kernel(const float* __restrict__ x, const float* __restrict__ A_log,
            const float* __restrict__ Dvec, float* __restrict__ y) {
    const int tid = threadIdx.x;
    const int j   = tid & 3;
    const int dloc = tid >> 2;          // 0..31
    const int b = blockIdx.x >> 6;
    const int d = (blockIdx.x & 63) * 32 + dloc;

    const float4 Al = *(const float4*)&A_log[d * NS + 4 * j];
    const float A0 = -__expf(Al.x), A1 = -__expf(Al.y);
    const float A2 = -__expf(Al.z), A3 = -__expf(Al.w);
    const float Dd = Dvec[d];

    const size_t rowBase = (size_t)b * LSEQ * DM + d;
    const float* xp  = x + rowBase;
    const float* dtp = g_dt + rowBase;
    const float4* bcp = (const float4*)(g_bc + (size_t)b * LSEQ * 32 + 8 * j);
    float* yp = y + rowBase;

    float h0 = 0.f, h1 = 0.f, h2 = 0.f, h3 = 0.f;

    float xv = *xp, dtv = *dtp;
    float4 bc0 = bcp[0], bc1 = bcp[1];

#pragma unroll 2
    for (int l = 0; l < LSEQ; l++) {
        float xn = 0.f, dtn = 0.f;
        float4 bn0 = make_float4(0.f, 0.f, 0.f, 0.f);
        float4 bn1 = make_float4(0.f, 0.f, 0.f, 0.f);
        if (l + 1 < LSEQ) {
            xn  = xp[DM];
            dtn = dtp[DM];
            bn0 = bcp[8];
            bn1 = bcp[9];
        }

        const float e0 = __expf(dtv * A0);
        const float e1 = __expf(dtv * A1);
        const float e2 = __expf(dtv * A2);
        const float e3 = __expf(dtv * A3);
        const float tx = dtv * xv;
        h0 = fmaf(e0, h0, tx * bc0.x);
        h1 = fmaf(e1, h1, tx * bc0.z);
        h2 = fmaf(e2, h2, tx * bc1.x);
        h3 = fmaf(e3, h3, tx * bc1.z);

        float p = h0 * bc0.y;
        p = fmaf(h1, bc0.w, p);
        p = fmaf(h2, bc1.y, p);
        p = fmaf(h3, bc1.w, p);
        p += __shfl_xor_sync(0xffffffffu, p, 1);
        p += __shfl_xor_sync(0xffffffffu, p, 2);
        if (j == 0) *yp = fmaf(Dd, xv, p);

        xp += DM; dtp += DM; bcp += 8; yp += DM;
        xv = xn; dtv = dtn; bc0 = bn0; bc1 = bn1;
    }
}

// ---------------- launch ----------------
extern "C" void kernel_launch(void* const* d_in, const int* in_sizes, int n_in,
                              void* d_out, int out_size) {
    const float* x      = (const float*)d_in[0];
    const float* A_log  = (const float*)d_in[1];
    const float* Dvec   = (const float*)d_in[2];
    const float* W      = (const float*)d_in[3];
    float* y            = (float*)d_out;

    (void)in_sizes; (void)n_in; (void)out_size;

    cudaFuncSetAttribute(gemm_hmma_kernel,
                         cudaFuncAttributeMaxDynamicSharedMemorySize, GEMM_SMEM);

    split_x_kernel<<<(unsigned)((size_t)MTOT * KTOT / 4 / 256), 256>>>(x);
    split_w_kernel<<<(unsigned)((size_t)ETPAD * KTOT / 4 / 256), 256>>>(W);

    dim3 ggrid(17, 64);
    gemm_hmma_kernel<<<ggrid, 256, GEMM_SMEM>>>();

    scan_kernel<<<256, 128>>>(x, A_log, Dvec, y);
}